// round 1
// baseline (speedup 1.0000x reference)
#include <cuda_runtime.h>

#define NQ    20
#define NPART 10
#define NB    128            // blocks in main kernel
#define CPB   (1024 / NB)    // columns (l-values) per block

// -------- device scratch (no allocations allowed) --------
__device__ float2 g_T1[1024];         // product of v_q over qubits 0..9, indexed by high bits of x
__device__ float2 g_T2[1024];         // product of v_q over qubits 10..19, indexed by low bits of x
__device__ int    g_XH[1024];         // f(h<<10): CNOT-inverse image of high index bits
__device__ int    g_XL[1024];         // f(l)    : CNOT-inverse image of low index bits
__device__ float2 g_V[40];            // fused Rx*Rz*Rx 2x2 per measured qubit (10 x 4 entries)
__device__ float  g_partial[NB][1024];

__device__ __forceinline__ float2 cmul(float2 a, float2 b) {
    return make_float2(a.x * b.x - a.y * b.y, a.x * b.y + a.y * b.x);
}
__device__ __forceinline__ float2 cadd(float2 a, float2 b) {
    return make_float2(a.x + b.x, a.y + b.y);
}

// ---------------------------------------------------------------------------
// Prep: build v_q columns, fused V matrices, T1/T2 product tables, and the
// GF(2) CNOT-inverse XOR tables. One block, 1024 threads.
// ---------------------------------------------------------------------------
__global__ void prep_kernel(const float* __restrict__ x, const float* __restrict__ w) {
    __shared__ float2 sv[NQ][2];   // encoding column per qubit
    __shared__ int    sFB[NQ];     // f(1<<p) for each index-bit position p

    const int tid = threadIdx.x;
    const float RS2  = 0.70710678118654752440f;   // 1/sqrt(2)
    const float WMUL = 0.63245553203367586640f;   // sqrt(2/5)

    if (tid < NQ) {
        // ---- encoding column v_q = Rz(atan(x^2)) * Ry(atan(x)) * H |0>
        const int q = tid;
        float xq = x[q];
        float th = atanf(xq);
        float c, s;
        sincosf(0.5f * th, &s, &c);
        float a = (c - s) * RS2;     // real amplitude before Rz, bit 0
        float b = (c + s) * RS2;     // bit 1
        float ph = 0.5f * atanf(xq * xq);
        float pc, ps;
        sincosf(ph, &ps, &pc);
        sv[q][0] = make_float2(a * pc, -a * ps);   // * e^{-i phi/2}
        sv[q][1] = make_float2(b * pc,  b * ps);   // * e^{+i phi/2}

        // ---- f = inverse of the CNOT-ring permutation, on basis bit p=tid.
        // state_after[y] = state_before[f(y)]; f applies the original CNOT
        // list in REVERSE order: for q=19..0: (q,q+2) then (q,q+1).
        // Index-bit space: qubit q <-> bit (19-q).
        int y = 1 << tid;
        for (int qq = NQ - 1; qq >= 0; --qq) {
            int cb  = 19 - qq;
            int tb2 = 19 - ((qq + 2) % NQ);
            int tb1 = 19 - ((qq + 1) % NQ);
            if ((y >> cb) & 1) y ^= (1 << tb2);
            if ((y >> cb) & 1) y ^= (1 << tb1);
        }
        sFB[tid] = y;
    }

    if (tid < NPART) {
        // ---- fused variational gate V = Rx(w2) * Rz(w1) * Rx(w0), measured qubits only
        const int q = tid;
        float w0 = w[3 * q + 0] * WMUL;
        float w1 = w[3 * q + 1] * WMUL;
        float w2 = w[3 * q + 2] * WMUL;
        float c0, s0, c1, s1, c2, s2;
        sincosf(0.5f * w0, &s0, &c0);
        sincosf(0.5f * w1, &s1, &c1);
        sincosf(0.5f * w2, &s2, &c2);
        // Rx(w0) = [[c0, -i s0],[-i s0, c0]]; Rz(w1) = diag(c1 - i s1, c1 + i s1)
        float2 r00 = make_float2(c0, 0.f), r01 = make_float2(0.f, -s0);
        float2 d0  = make_float2(c1, -s1), d1  = make_float2(c1,  s1);
        float2 A00 = cmul(d0, r00), A01 = cmul(d0, r01);
        float2 A10 = cmul(d1, r01), A11 = cmul(d1, r00);
        // M = Rx(w2) * A
        float2 m = make_float2(0.f, -s2);
        g_V[4 * q + 0] = cadd(make_float2(c2 * A00.x, c2 * A00.y), cmul(m, A10));
        g_V[4 * q + 1] = cadd(make_float2(c2 * A01.x, c2 * A01.y), cmul(m, A11));
        g_V[4 * q + 2] = cadd(cmul(m, A00), make_float2(c2 * A10.x, c2 * A10.y));
        g_V[4 * q + 3] = cadd(cmul(m, A01), make_float2(c2 * A11.x, c2 * A11.y));
    }

    __syncthreads();

    // ---- per-thread table entries (a = tid in 0..1023)
    const int a = tid;
    float2 p1 = make_float2(1.f, 0.f);
    float2 p2 = make_float2(1.f, 0.f);
#pragma unroll
    for (int q = 0; q < NPART; ++q)
        p1 = cmul(p1, sv[q][(a >> (9 - q)) & 1]);
#pragma unroll
    for (int q = NPART; q < NQ; ++q)
        p2 = cmul(p2, sv[q][(a >> (19 - q)) & 1]);
    g_T1[a] = p1;
    g_T2[a] = p2;

    int xl = 0, xh = 0;
#pragma unroll
    for (int p = 0; p < 10; ++p) {
        if ((a >> p) & 1) { xl ^= sFB[p]; xh ^= sFB[p + 10]; }
    }
    g_XL[a] = xl;
    g_XH[a] = xh;
}

// ---------------------------------------------------------------------------
// Main: each block processes CPB columns l. For each l, synthesize the
// 1024-entry column (state after encoding+CNOTs), run the 10-stage butterfly
// of the measured qubits' gates, accumulate |amp|^2 into per-block partials.
// ---------------------------------------------------------------------------
__global__ void __launch_bounds__(512) sim_kernel() {
    __shared__ float2 s[1024];
    __shared__ float2 t1s[1024];
    __shared__ float2 t2s[1024];
    __shared__ float2 sV[40];

    const int tid = threadIdx.x;   // 0..511

    t1s[tid]       = g_T1[tid];
    t1s[tid + 512] = g_T1[tid + 512];
    t2s[tid]       = g_T2[tid];
    t2s[tid + 512] = g_T2[tid + 512];
    if (tid < 40) sV[tid] = g_V[tid];
    const int xh0 = g_XH[tid];
    const int xh1 = g_XH[tid + 512];
    __syncthreads();

    float acc0 = 0.f, acc1 = 0.f;

    for (int j = 0; j < CPB; ++j) {
        const int l  = blockIdx.x * CPB + j;
        const int xl = g_XL[l];

        // synthesize column: amp(h,l) = T1[x>>10] * T2[x&1023], x = XH[h]^XL[l]
        {
            int x0 = xh0 ^ xl;
            s[tid] = cmul(t1s[x0 >> 10], t2s[x0 & 1023]);
            int x1 = xh1 ^ xl;
            s[tid + 512] = cmul(t1s[x1 >> 10], t2s[x1 & 1023]);
        }
        __syncthreads();

        // 10 butterfly stages: bit b of h carries qubit q = 9-b
#pragma unroll
        for (int b = 0; b < 10; ++b) {
            const int q  = 9 - b;
            const int lo = tid & ((1 << b) - 1);
            const int h0 = ((tid >> b) << (b + 1)) | lo;
            const int h1 = h0 | (1 << b);
            float2 a0 = s[h0];
            float2 a1 = s[h1];
            float2 V00 = sV[4 * q + 0], V01 = sV[4 * q + 1];
            float2 V10 = sV[4 * q + 2], V11 = sV[4 * q + 3];
            s[h0] = cadd(cmul(V00, a0), cmul(V01, a1));
            s[h1] = cadd(cmul(V10, a0), cmul(V11, a1));
            __syncthreads();
        }

        float2 u0 = s[tid];
        float2 u1 = s[tid + 512];
        acc0 += u0.x * u0.x + u0.y * u0.y;
        acc1 += u1.x * u1.x + u1.y * u1.y;
        // no extra barrier: s[tid] / s[tid+512] are written next iteration
        // only by their owning thread (same thread that just read them)
    }

    g_partial[blockIdx.x][tid]       = acc0;
    g_partial[blockIdx.x][tid + 512] = acc1;
}

// deterministic cross-block reduction
__global__ void reduce_kernel(float* __restrict__ out) {
    const int h = threadIdx.x + blockIdx.x * blockDim.x;
    float acc = 0.f;
#pragma unroll
    for (int b = 0; b < NB; ++b) acc += g_partial[b][h];
    out[h] = acc;
}

extern "C" void kernel_launch(void* const* d_in, const int* in_sizes, int n_in,
                              void* d_out, int out_size) {
    const float* x = (const float*)d_in[0];   // (1, 20) float32
    const float* w = (const float*)d_in[1];   // (60,)  float32
    float* out = (float*)d_out;               // (1, 1024) float32

    prep_kernel<<<1, 1024>>>(x, w);
    sim_kernel<<<NB, 512>>>();
    reduce_kernel<<<1, 1024>>>(out);
}

// round 2
// speedup vs baseline: 1.6212x; 1.6212x over previous
#include <cuda_runtime.h>

#define NQ    20
#define NPART 10
#define NB    128          // blocks in sim kernel
#define WPB   8            // warps per block -> 1024 warp-columns total
#define TPB   256

__device__ float g_partial[NB][1024];

__device__ __forceinline__ float2 cmul(float2 a, float2 b) {
    return make_float2(a.x * b.x - a.y * b.y, a.x * b.y + a.y * b.x);
}
__device__ __forceinline__ float2 cadd(float2 a, float2 b) {
    return make_float2(a.x + b.x, a.y + b.y);
}

// ---------------------------------------------------------------------------
// One fused kernel: per-block (redundant, cheap) prep of encoding columns,
// fused variational 2x2 gates, CNOT-inverse XOR basis, and product tables;
// then each warp simulates one column l: synthesizes 1024 amps (32/thread in
// registers), runs 5 register butterfly stages + 5 shfl butterfly stages,
// accumulates |amp|^2 into shared, block-reduces to a per-block partial.
// ---------------------------------------------------------------------------
__global__ void __launch_bounds__(TPB) sim_kernel(const float* __restrict__ x,
                                                  const float* __restrict__ w) {
    __shared__ float2 sT1[1024];
    __shared__ float2 sT2[1024];
    __shared__ float2 sv[NQ][2];
    __shared__ int    sFB[NQ];
    __shared__ float2 sV[40];
    __shared__ int    sXHlo[32];
    __shared__ float  sacc[WPB][32 * 33];   // padded stride 33 -> conflict-free

    const int tid  = threadIdx.x;
    const int warp = tid >> 5;
    const int lane = tid & 31;

    const float RS2  = 0.70710678118654752440f;   // 1/sqrt(2)
    const float WMUL = 0.63245553203367586640f;   // sqrt(2/5)

    if (tid < NQ) {
        // encoding column v_q = Rz(atan(x^2)) * Ry(atan(x)) * H |0>
        const int q = tid;
        float xq = x[q];
        float th = atanf(xq);
        float c, s;
        sincosf(0.5f * th, &s, &c);
        float a = (c - s) * RS2;
        float b = (c + s) * RS2;
        float ph = 0.5f * atanf(xq * xq);
        float pc, ps;
        sincosf(ph, &ps, &pc);
        sv[q][0] = make_float2(a * pc, -a * ps);
        sv[q][1] = make_float2(b * pc,  b * ps);

        // f = inverse CNOT-ring permutation on basis bit p=tid
        int y = 1 << tid;
        for (int qq = NQ - 1; qq >= 0; --qq) {
            int cb  = 19 - qq;
            int tb2 = 19 - ((qq + 2) % NQ);
            int tb1 = 19 - ((qq + 1) % NQ);
            if ((y >> cb) & 1) y ^= (1 << tb2);
            if ((y >> cb) & 1) y ^= (1 << tb1);
        }
        sFB[tid] = y;
    }

    if (tid < NPART) {
        // fused variational gate V = Rx(w2) * Rz(w1) * Rx(w0) on measured qubits
        const int q = tid;
        float w0 = w[3 * q + 0] * WMUL;
        float w1 = w[3 * q + 1] * WMUL;
        float w2 = w[3 * q + 2] * WMUL;
        float c0, s0, c1, s1, c2, s2;
        sincosf(0.5f * w0, &s0, &c0);
        sincosf(0.5f * w1, &s1, &c1);
        sincosf(0.5f * w2, &s2, &c2);
        float2 r00 = make_float2(c0, 0.f), r01 = make_float2(0.f, -s0);
        float2 d0  = make_float2(c1, -s1), d1  = make_float2(c1,  s1);
        float2 A00 = cmul(d0, r00), A01 = cmul(d0, r01);
        float2 A10 = cmul(d1, r01), A11 = cmul(d1, r00);
        float2 m = make_float2(0.f, -s2);
        sV[4 * q + 0] = cadd(make_float2(c2 * A00.x, c2 * A00.y), cmul(m, A10));
        sV[4 * q + 1] = cadd(make_float2(c2 * A01.x, c2 * A01.y), cmul(m, A11));
        sV[4 * q + 2] = cadd(cmul(m, A00), make_float2(c2 * A10.x, c2 * A10.y));
        sV[4 * q + 3] = cadd(cmul(m, A01), make_float2(c2 * A11.x, c2 * A11.y));
    }
    __syncthreads();

    // product tables (4 entries per thread) + low-bit XOR basis table
#pragma unroll
    for (int a = tid; a < 1024; a += TPB) {
        float2 p1 = make_float2(1.f, 0.f);
        float2 p2 = make_float2(1.f, 0.f);
#pragma unroll
        for (int q = 0; q < NPART; ++q)
            p1 = cmul(p1, sv[q][(a >> (9 - q)) & 1]);
#pragma unroll
        for (int q = NPART; q < NQ; ++q)
            p2 = cmul(p2, sv[q][(a >> (19 - q)) & 1]);
        sT1[a] = p1;
        sT2[a] = p2;
    }
    if (tid < 32) {
        int v = 0;
#pragma unroll
        for (int i = 0; i < 5; ++i)
            if ((tid >> i) & 1) v ^= sFB[10 + i];
        sXHlo[tid] = v;
    }
    __syncthreads();

    // ---- this warp's column
    const int l = blockIdx.x * WPB + warp;
    int xl = 0;
#pragma unroll
    for (int j = 0; j < 10; ++j)
        if ((l >> j) & 1) xl ^= sFB[j];
    int xhhi = 0;
#pragma unroll
    for (int p = 0; p < 5; ++p)
        if ((lane >> p) & 1) xhhi ^= sFB[15 + p];
    const int xbase = xhhi ^ xl;

    // synthesize 32 amps/thread: h = (lane<<5) | r
    float2 a[32];
#pragma unroll
    for (int r = 0; r < 32; ++r) {
        int xx = xbase ^ sXHlo[r];
        a[r] = cmul(sT1[xx >> 10], sT2[xx & 1023]);
    }

    // 5 register stages: h bit b (b=0..4), gate q = 9-b
#pragma unroll
    for (int b = 0; b < 5; ++b) {
        const int q = 9 - b;
        float2 V00 = sV[4 * q + 0], V01 = sV[4 * q + 1];
        float2 V10 = sV[4 * q + 2], V11 = sV[4 * q + 3];
#pragma unroll
        for (int g = 0; g < 16; ++g) {
            int lo = g & ((1 << b) - 1);
            int r0 = ((g >> b) << (b + 1)) | lo;
            int r1 = r0 | (1 << b);
            float2 a0 = a[r0];
            float2 a1 = a[r1];
            a[r0] = cadd(cmul(V00, a0), cmul(V01, a1));
            a[r1] = cadd(cmul(V10, a0), cmul(V11, a1));
        }
    }

    // 5 shuffle stages: h bit 5+p (lane bit p), gate q = 4-p
#pragma unroll
    for (int p = 0; p < 5; ++p) {
        const int q = 4 - p;
        float2 V00 = sV[4 * q + 0], V01 = sV[4 * q + 1];
        float2 V10 = sV[4 * q + 2], V11 = sV[4 * q + 3];
        const int bit = (lane >> p) & 1;
        const float2 Vs = bit ? V11 : V00;
        const float2 Vo = bit ? V10 : V01;
#pragma unroll
        for (int r = 0; r < 32; ++r) {
            float2 o;
            o.x = __shfl_xor_sync(0xffffffffu, a[r].x, 1 << p);
            o.y = __shfl_xor_sync(0xffffffffu, a[r].y, 1 << p);
            a[r] = cadd(cmul(Vs, a[r]), cmul(Vo, o));
        }
    }

    // |amp|^2 into padded per-warp shared slice
#pragma unroll
    for (int r = 0; r < 32; ++r)
        sacc[warp][lane * 33 + r] = a[r].x * a[r].x + a[r].y * a[r].y;
    __syncthreads();

    // deterministic block reduce over the 8 warps
#pragma unroll
    for (int h = tid; h < 1024; h += TPB) {
        const int lh = h >> 5;
        const int rr = h & 31;
        float s = 0.f;
#pragma unroll
        for (int ww = 0; ww < WPB; ++ww)
            s += sacc[ww][lh * 33 + rr];
        g_partial[blockIdx.x][h] = s;
    }
}

// deterministic cross-block reduction, parallel over 8 blocks
__global__ void reduce_kernel(float* __restrict__ out) {
    const int h = threadIdx.x + blockIdx.x * blockDim.x;
    float acc = 0.f;
#pragma unroll
    for (int b = 0; b < NB; ++b) acc += g_partial[b][h];
    out[h] = acc;
}

extern "C" void kernel_launch(void* const* d_in, const int* in_sizes, int n_in,
                              void* d_out, int out_size) {
    const float* x = (const float*)d_in[0];   // (1, 20) float32
    const float* w = (const float*)d_in[1];   // (60,)  float32
    float* out = (float*)d_out;               // (1, 1024) float32

    sim_kernel<<<NB, TPB>>>(x, w);
    reduce_kernel<<<8, 128>>>(out);
}